// round 15
// baseline (speedup 1.0000x reference)
#include <cuda_runtime.h>
#include <cuda_fp16.h>
#include <math.h>
#include <stdint.h>

// Problem constants
#define BB   2
#define SS   4096
#define HID  768
#define NL   4
#define NH   12
#define HD   64
#define AW   128
#define ROWS (BB*SS)      // 8192

// ---------------------------------------------------------------------------
// Scratch
// ---------------------------------------------------------------------------
#define ACT (ROWS*HID)
#define WT_SM (NL*HID*HID)
#define WT_LG (NL*HID*4*HID)
__device__ float g_scratch[9*(size_t)ACT + 4*(size_t)WT_SM + 2*(size_t)WT_LG];

// ---------------------------------------------------------------------------
// helpers
// ---------------------------------------------------------------------------
__device__ __forceinline__ uint32_t smem_u32(const void* p){
    uint32_t a;
    asm("{ .reg .u64 t; cvta.to.shared.u64 t, %1; cvt.u32.u64 %0, t; }" : "=r"(a) : "l"(p));
    return a;
}
#define CP_ASYNC16(dst,src)      asm volatile("cp.async.cg.shared.global [%0], [%1], 16;" :: "r"(dst), "l"(src))
#define CP_ASYNC16Z(dst,src,nb)  asm volatile("cp.async.cg.shared.global [%0], [%1], 16, %2;" :: "r"(dst), "l"(src), "r"(nb))
#define CP_COMMIT() asm volatile("cp.async.commit_group;" ::: "memory")
#define LDSM4(r, a) \
    asm volatile("ldmatrix.sync.aligned.m8n8.x4.shared.b16 {%0,%1,%2,%3}, [%4];" \
        : "=r"((r)[0]),"=r"((r)[1]),"=r"((r)[2]),"=r"((r)[3]) : "r"(a))
#define LDSM2T(r, a) \
    asm volatile("ldmatrix.sync.aligned.m8n8.x2.trans.shared.b16 {%0,%1}, [%2];" \
        : "=r"((r)[0]),"=r"((r)[1]) : "r"(a))

__device__ __forceinline__ void mma_f16(float* d, const uint32_t* a, const uint32_t* b){
    asm volatile("mma.sync.aligned.m16n8k16.row.col.f32.f16.f16.f32 "
        "{%0,%1,%2,%3}, {%4,%5,%6,%7}, {%8,%9}, {%0,%1,%2,%3};"
        : "+f"(d[0]),"+f"(d[1]),"+f"(d[2]),"+f"(d[3])
        : "r"(a[0]),"r"(a[1]),"r"(a[2]),"r"(a[3]), "r"(b[0]),"r"(b[1]));
}
__device__ __forceinline__ float gelu_exact(float x){
    return 0.5f * x * (1.f + erff(x * 0.70710678118654752f));
}
__device__ __forceinline__ float wred_sum(float v){
#pragma unroll
    for (int o = 16; o > 0; o >>= 1) v += __shfl_xor_sync(~0u, v, o);
    return v;
}

// ---------------------------------------------------------------------------
// fp16 mma.sync GEMM 128x128 (qkv / Wi).
// mode bits: 1 = gelu, 2 = fp16 output, 4 = qkv bias select
// ---------------------------------------------------------------------------
#define GBM 128
#define GBN 128
#define GBK 32
#define NSTG 3
#define STG  (2*GBM*80)
#define GEMM_SMEM (NSTG*STG)

__device__ __forceinline__ void load_chunk16(const __half* __restrict__ A, const __half* __restrict__ BT,
                                             int K, int bm, int bn, int c, uint32_t stage)
{
    int t = threadIdx.x;
    const __half* asrc = A  + (size_t)bm*K + (size_t)c*GBK;
    const __half* bsrc = BT + (size_t)bn*K + (size_t)c*GBK;
#pragma unroll
    for (int i = 0; i < 4; i++){
        int idx = i*128 + t;
        int row = idx >> 2, seg = idx & 3;
        CP_ASYNC16(stage + row*80 + seg*16, asrc + (size_t)row*K + seg*8);
    }
#pragma unroll
    for (int i = 0; i < 4; i++){
        int idx = i*128 + t;
        int row = idx >> 2, seg = idx & 3;
        CP_ASYNC16(stage + GBM*80 + row*80 + seg*16, bsrc + (size_t)row*K + seg*8);
    }
    CP_COMMIT();
}

__global__ __launch_bounds__(128, 2)
void gemm_tc(const __half* __restrict__ A, const __half* __restrict__ BT,
             const float* __restrict__ bias, const float* __restrict__ bK,
             const float* __restrict__ bV, void* __restrict__ Cv,
             int K, int N, int mode)
{
    extern __shared__ char smem[];
    int t = threadIdx.x;
    int wid = t >> 5, lane = t & 31;
    int grp = lane >> 2, q4 = lane & 3;
    int mw = (wid & 1) * 64, nw = (wid >> 1) * 64;
    int bm = blockIdx.y * GBM, bn = blockIdx.x * GBN;

    int lm = lane >> 3, lr = lane & 7;
    uint32_t aoff = (uint32_t)(((lm & 1)*8 + lr)*80 + (lm >> 1)*16);
    uint32_t boff = (uint32_t)(((lm >> 1)*8 + lr)*80 + (lm & 1)*16);

    float acc[4][8][4];
#pragma unroll
    for (int mi = 0; mi < 4; mi++)
#pragma unroll
        for (int ni = 0; ni < 8; ni++)
#pragma unroll
            for (int r = 0; r < 4; r++) acc[mi][ni][r] = 0.f;

    uint32_t sb = smem_u32(smem);
    const int NC = K / GBK;

    load_chunk16(A, BT, K, bm, bn, 0, sb);
    load_chunk16(A, BT, K, bm, bn, 1, sb + STG);

    for (int c = 0; c < NC; c++){
        int slot = c % NSTG;
        if (c + 1 < NC) { asm volatile("cp.async.wait_group 1;" ::: "memory"); }
        else            { asm volatile("cp.async.wait_group 0;" ::: "memory"); }
        __syncthreads();
        if (c + 2 < NC)
            load_chunk16(A, BT, K, bm, bn, c + 2, sb + ((c+2)%NSTG)*STG);

        uint32_t As_b = sb + slot*STG;
        uint32_t Bs_b = As_b + GBM*80;
#pragma unroll
        for (int ks = 0; ks < 2; ks++){
            uint32_t kb = ks*32;
            uint32_t af[4][4], bf[8][2];
#pragma unroll
            for (int mi = 0; mi < 4; mi++)
                LDSM4(af[mi], As_b + (mw + mi*16)*80 + aoff + kb);
#pragma unroll
            for (int p = 0; p < 4; p++){
                uint32_t r[4];
                LDSM4(r, Bs_b + (nw + p*16)*80 + boff + kb);
                bf[2*p][0] = r[0]; bf[2*p][1] = r[1];
                bf[2*p+1][0] = r[2]; bf[2*p+1][1] = r[3];
            }
#pragma unroll
            for (int mi = 0; mi < 4; mi++)
#pragma unroll
                for (int ni = 0; ni < 8; ni++)
                    mma_f16(acc[mi][ni], af[mi], bf[ni]);
        }
    }

    const float* bp = bias;
    int coff = 0;
    if (mode & 4){
        int sel = bn / HID;
        bp = (sel == 0) ? bias : (sel == 1 ? bK : bV);
        coff = sel * HID;
    }

    float* Cf = (float*)Cv;
    __half* Ch = (__half*)Cv;
#pragma unroll
    for (int mi = 0; mi < 4; mi++){
        int r0 = bm + mw + mi*16 + grp;
#pragma unroll
        for (int ni = 0; ni < 8; ni++){
            int col = bn + nw + ni*8 + 2*q4;
            float bx = bp[col - coff], by = bp[col + 1 - coff];
            float a0 = acc[mi][ni][0] + bx, a1 = acc[mi][ni][1] + by;
            float a2 = acc[mi][ni][2] + bx, a3 = acc[mi][ni][3] + by;
            if (mode & 1){
                a0 = gelu_exact(a0); a1 = gelu_exact(a1);
                a2 = gelu_exact(a2); a3 = gelu_exact(a3);
            }
            if (mode & 2){
                *(__half2*)&Ch[(size_t)r0*N + col]     = __floats2half2_rn(a0, a1);
                *(__half2*)&Ch[(size_t)(r0+8)*N + col] = __floats2half2_rn(a2, a3);
            } else {
                *(float2*)&Cf[(size_t)r0*N + col]     = make_float2(a0, a1);
                *(float2*)&Cf[(size_t)(r0+8)*N + col] = make_float2(a2, a3);
            }
        }
    }
}

// ---------------------------------------------------------------------------
// fp16 GEMM 128x64 tile, 3 CTAs/SM (N=768 GEMMs).
// ---------------------------------------------------------------------------
#define STG64 ((GBM + 64)*80)
#define GEMM64_SMEM (NSTG*STG64)

__device__ __forceinline__ void load_chunk64(const __half* __restrict__ A, const __half* __restrict__ BT,
                                             int K, int bm, int bn, int c, uint32_t stage)
{
    int t = threadIdx.x;
    const __half* asrc = A  + (size_t)bm*K + (size_t)c*GBK;
    const __half* bsrc = BT + (size_t)bn*K + (size_t)c*GBK;
#pragma unroll
    for (int i = 0; i < 4; i++){
        int idx = i*128 + t;
        int row = idx >> 2, seg = idx & 3;
        CP_ASYNC16(stage + row*80 + seg*16, asrc + (size_t)row*K + seg*8);
    }
#pragma unroll
    for (int i = 0; i < 2; i++){
        int idx = i*128 + t;
        int row = idx >> 2, seg = idx & 3;
        CP_ASYNC16(stage + GBM*80 + row*80 + seg*16, bsrc + (size_t)row*K + seg*8);
    }
    CP_COMMIT();
}

__global__ __launch_bounds__(128, 3)
void gemm_tc64(const __half* __restrict__ A, const __half* __restrict__ BT,
               const float* __restrict__ bias, __half* __restrict__ C,
               int K, int N, int mode)
{
    extern __shared__ char smem[];
    int t = threadIdx.x;
    int wid = t >> 5, lane = t & 31;
    int grp = lane >> 2, q4 = lane & 3;
    int mw = (wid & 1) * 64, nw = (wid >> 1) * 32;
    int bm = blockIdx.y * GBM, bn = blockIdx.x * 64;

    int lm = lane >> 3, lr = lane & 7;
    uint32_t aoff = (uint32_t)(((lm & 1)*8 + lr)*80 + (lm >> 1)*16);
    uint32_t boff = (uint32_t)(((lm >> 1)*8 + lr)*80 + (lm & 1)*16);

    float acc[4][4][4];
#pragma unroll
    for (int mi = 0; mi < 4; mi++)
#pragma unroll
        for (int ni = 0; ni < 4; ni++)
#pragma unroll
            for (int r = 0; r < 4; r++) acc[mi][ni][r] = 0.f;

    uint32_t sb = smem_u32(smem);
    const int NC = K / GBK;

    load_chunk64(A, BT, K, bm, bn, 0, sb);
    load_chunk64(A, BT, K, bm, bn, 1, sb + STG64);

    for (int c = 0; c < NC; c++){
        int slot = c % NSTG;
        if (c + 1 < NC) { asm volatile("cp.async.wait_group 1;" ::: "memory"); }
        else            { asm volatile("cp.async.wait_group 0;" ::: "memory"); }
        __syncthreads();
        if (c + 2 < NC)
            load_chunk64(A, BT, K, bm, bn, c + 2, sb + ((c+2)%NSTG)*STG64);

        uint32_t As_b = sb + slot*STG64;
        uint32_t Bs_b = As_b + GBM*80;
#pragma unroll
        for (int ks = 0; ks < 2; ks++){
            uint32_t kb = ks*32;
            uint32_t af[4][4], bf[4][2];
#pragma unroll
            for (int mi = 0; mi < 4; mi++)
                LDSM4(af[mi], As_b + (mw + mi*16)*80 + aoff + kb);
#pragma unroll
            for (int p = 0; p < 2; p++){
                uint32_t r[4];
                LDSM4(r, Bs_b + (nw + p*16)*80 + boff + kb);
                bf[2*p][0] = r[0]; bf[2*p][1] = r[1];
                bf[2*p+1][0] = r[2]; bf[2*p+1][1] = r[3];
            }
#pragma unroll
            for (int mi = 0; mi < 4; mi++)
#pragma unroll
                for (int ni = 0; ni < 4; ni++)
                    mma_f16(acc[mi][ni], af[mi], bf[ni]);
        }
    }

#pragma unroll
    for (int mi = 0; mi < 4; mi++){
        int r0 = bm + mw + mi*16 + grp;
#pragma unroll
        for (int ni = 0; ni < 4; ni++){
            int col = bn + nw + ni*8 + 2*q4;
            float bx = bias[col], by = bias[col+1];
            float a0 = acc[mi][ni][0] + bx, a1 = acc[mi][ni][1] + by;
            float a2 = acc[mi][ni][2] + bx, a3 = acc[mi][ni][3] + by;
            if (mode & 1){
                a0 = gelu_exact(a0); a1 = gelu_exact(a1);
                a2 = gelu_exact(a2); a3 = gelu_exact(a3);
            }
            *(__half2*)&C[(size_t)r0*N + col]     = __floats2half2_rn(a0, a1);
            *(__half2*)&C[(size_t)(r0+8)*N + col] = __floats2half2_rn(a2, a3);
        }
    }
}

// ---------------------------------------------------------------------------
// Weight transposes to fp16
// ---------------------------------------------------------------------------
__global__ __launch_bounds__(256)
void transpose_h(const float* __restrict__ in, __half* __restrict__ out,
                 int R, int C, size_t outStride)
{
    __shared__ float tile[32][33];
    const float* src = in  + (size_t)blockIdx.z * R * C;
    __half*      dst = out + (size_t)blockIdx.z * outStride;
    int r0 = blockIdx.y*32, c0 = blockIdx.x*32;
    int tx = threadIdx.x & 31, ty = threadIdx.x >> 5;
#pragma unroll
    for (int i = 0; i < 4; i++)
        tile[ty + i*8][tx] = src[(size_t)(r0 + ty + i*8)*C + c0 + tx];
    __syncthreads();
#pragma unroll
    for (int i = 0; i < 4; i++)
        dst[(size_t)(c0 + ty + i*8)*R + r0 + tx] = __float2half(tile[tx][ty + i*8]);
}

__global__ __launch_bounds__(256)
void transpose_qkv(const float* __restrict__ Wq, const float* __restrict__ Wk,
                   const float* __restrict__ Wv, __half* __restrict__ out)
{
    __shared__ float tile[32][33];
    int z = blockIdx.z;
    int m = z / NL, l = z % NL;
    const float* src = (m == 0 ? Wq : (m == 1 ? Wk : Wv)) + (size_t)l*HID*HID;
    __half* dst = out + (size_t)l*3*HID*HID + (size_t)m*HID*HID;
    int r0 = blockIdx.y*32, c0 = blockIdx.x*32;
    int tx = threadIdx.x & 31, ty = threadIdx.x >> 5;
#pragma unroll
    for (int i = 0; i < 4; i++)
        tile[ty + i*8][tx] = src[(size_t)(r0 + ty + i*8)*HID + c0 + tx];
    __syncthreads();
#pragma unroll
    for (int i = 0; i < 4; i++)
        dst[(size_t)(c0 + ty + i*8)*HID + r0 + tx] = __float2half(tile[tx][ty + i*8]);
}

// ---------------------------------------------------------------------------
// Warp-per-row LayerNorm kernels
// ---------------------------------------------------------------------------
__global__ __launch_bounds__(256)
void embed_ln_kernel(const float* __restrict__ emb, const float* __restrict__ pos,
                     const float* __restrict__ tok, const float* __restrict__ gam,
                     const float* __restrict__ bet, float* __restrict__ h,
                     __half* __restrict__ h16)
{
    int w = threadIdx.x >> 5, lane = threadIdx.x & 31;
    int r = blockIdx.x*8 + w;
    int s = r & (SS-1);
    const float* er = emb + (size_t)r*HID;
    const float* pr = pos + (size_t)(s+1)*HID;

    float x[24];
    float sum = 0.f;
#pragma unroll
    for (int i = 0; i < 6; i++){
        int c = i*128 + lane*4;
        float4 e = *(const float4*)&er[c];
        float4 p = *(const float4*)&pr[c];
        float4 tk = *(const float4*)&tok[c];
        x[i*4+0] = e.x + p.x + tk.x;
        x[i*4+1] = e.y + p.y + tk.y;
        x[i*4+2] = e.z + p.z + tk.z;
        x[i*4+3] = e.w + p.w + tk.w;
        sum += x[i*4+0] + x[i*4+1] + x[i*4+2] + x[i*4+3];
    }
    float mean = wred_sum(sum) * (1.f/HID);
    float vs = 0.f;
#pragma unroll
    for (int i = 0; i < 24; i++){ float d = x[i] - mean; vs += d*d; }
    float inv = rsqrtf(wred_sum(vs) * (1.f/HID) + 1e-12f);

    float* hr = h + (size_t)r*HID;
    __half* h16r = h16 + (size_t)r*HID;
#pragma unroll
    for (int i = 0; i < 6; i++){
        int c = i*128 + lane*4;
        float4 g = *(const float4*)&gam[c];
        float4 b = *(const float4*)&bet[c];
        float4 o;
        o.x = (x[i*4+0] - mean)*inv*g.x + b.x;
        o.y = (x[i*4+1] - mean)*inv*g.y + b.y;
        o.z = (x[i*4+2] - mean)*inv*g.z + b.z;
        o.w = (x[i*4+3] - mean)*inv*g.w + b.w;
        *(float4*)&hr[c] = o;
        *(__half2*)&h16r[c]   = __floats2half2_rn(o.x, o.y);
        *(__half2*)&h16r[c+2] = __floats2half2_rn(o.z, o.w);
    }
}

__global__ __launch_bounds__(256)
void add_ln_kernel(const float* __restrict__ hin, const __half* __restrict__ tin,
                   const float* __restrict__ gam, const float* __restrict__ bet,
                   float* __restrict__ hout, __half* __restrict__ h16)
{
    int w = threadIdx.x >> 5, lane = threadIdx.x & 31;
    int r = blockIdx.x*8 + w;
    const float* ar = hin + (size_t)r*HID;
    const __half* br = tin + (size_t)r*HID;

    float x[24];
    float sum = 0.f;
#pragma unroll
    for (int i = 0; i < 6; i++){
        int c = i*128 + lane*4;
        float4 a = *(const float4*)&ar[c];
        __half2 b0 = *(const __half2*)&br[c];
        __half2 b1 = *(const __half2*)&br[c+2];
        float2 f0 = __half22float2(b0), f1 = __half22float2(b1);
        x[i*4+0] = a.x + f0.x; x[i*4+1] = a.y + f0.y;
        x[i*4+2] = a.z + f1.x; x[i*4+3] = a.w + f1.y;
        sum += x[i*4+0] + x[i*4+1] + x[i*4+2] + x[i*4+3];
    }
    float mean = wred_sum(sum) * (1.f/HID);
    float vs = 0.f;
#pragma unroll
    for (int i = 0; i < 24; i++){ float d = x[i] - mean; vs += d*d; }
    float inv = rsqrtf(wred_sum(vs) * (1.f/HID) + 1e-12f);

    float* hr = hout + (size_t)r*HID;
    __half* h16r = h16 + (size_t)r*HID;
#pragma unroll
    for (int i = 0; i < 6; i++){
        int c = i*128 + lane*4;
        float4 g = *(const float4*)&gam[c];
        float4 b = *(const float4*)&bet[c];
        float4 o;
        o.x = (x[i*4+0] - mean)*inv*g.x + b.x;
        o.y = (x[i*4+1] - mean)*inv*g.y + b.y;
        o.z = (x[i*4+2] - mean)*inv*g.z + b.z;
        o.w = (x[i*4+3] - mean)*inv*g.w + b.w;
        *(float4*)&hr[c] = o;
        *(__half2*)&h16r[c]   = __floats2half2_rn(o.x, o.y);
        *(__half2*)&h16r[c+2] = __floats2half2_rn(o.z, o.w);
    }
}

// Last layer: residual + LN fused with classifier head (dot Wp + sigmoid).
// No h/h16 writes.
__global__ __launch_bounds__(256)
void add_ln_final_kernel(const float* __restrict__ hin, const __half* __restrict__ tin,
                         const float* __restrict__ gam, const float* __restrict__ bet,
                         const float* __restrict__ Wp, const float* __restrict__ bp,
                         float* __restrict__ out)
{
    int w = threadIdx.x >> 5, lane = threadIdx.x & 31;
    int r = blockIdx.x*8 + w;
    const float* ar = hin + (size_t)r*HID;
    const __half* br = tin + (size_t)r*HID;

    float x[24];
    float sum = 0.f;
#pragma unroll
    for (int i = 0; i < 6; i++){
        int c = i*128 + lane*4;
        float4 a = *(const float4*)&ar[c];
        __half2 b0 = *(const __half2*)&br[c];
        __half2 b1 = *(const __half2*)&br[c+2];
        float2 f0 = __half22float2(b0), f1 = __half22float2(b1);
        x[i*4+0] = a.x + f0.x; x[i*4+1] = a.y + f0.y;
        x[i*4+2] = a.z + f1.x; x[i*4+3] = a.w + f1.y;
        sum += x[i*4+0] + x[i*4+1] + x[i*4+2] + x[i*4+3];
    }
    float mean = wred_sum(sum) * (1.f/HID);
    float vs = 0.f;
#pragma unroll
    for (int i = 0; i < 24; i++){ float d = x[i] - mean; vs += d*d; }
    float inv = rsqrtf(wred_sum(vs) * (1.f/HID) + 1e-12f);

    float dot = 0.f;
#pragma unroll
    for (int i = 0; i < 6; i++){
        int c = i*128 + lane*4;
        float4 g = *(const float4*)&gam[c];
        float4 b = *(const float4*)&bet[c];
        float4 wv = *(const float4*)&Wp[c];
        dot += ((x[i*4+0] - mean)*inv*g.x + b.x) * wv.x;
        dot += ((x[i*4+1] - mean)*inv*g.y + b.y) * wv.y;
        dot += ((x[i*4+2] - mean)*inv*g.z + b.z) * wv.z;
        dot += ((x[i*4+3] - mean)*inv*g.w + b.w) * wv.w;
    }
    dot = wred_sum(dot);
    if (lane == 0) out[r] = 1.f / (1.f + expf(-(dot + bp[0])));
}

// ---------------------------------------------------------------------------
// fp16 tensor-core sliding-window attention (2 CTAs/SM, aliased sQ/sP).
// ---------------------------------------------------------------------------
#define QT    32
#define KW    320
#define KVSH  72
#define SSTR  328
#define SPSTR 344
#define SKV_B  0
#define SS_B   (KW*KVSH*2)
#define SP_B   (SS_B + QT*SSTR*4)
#define SQ_B   SP_B
#define SM_B   (SP_B + QT*SPSTR*2)
#define ATT_SMEM (SM_B + KW)

__global__ __launch_bounds__(256)
void attn_kernel(const __half* __restrict__ qkv16, const int* __restrict__ km,
                 __half* __restrict__ ag16)
{
    int qt   = blockIdx.x;
    int head = blockIdx.y;
    int b    = blockIdx.z;
    int q0   = qt * QT;
    int kbase = q0 - AW;

    extern __shared__ char smraw[];
    __half* sKV = (__half*)(smraw + SKV_B);
    float*  sS  = (float*)(smraw + SS_B);
    __half* sP  = (__half*)(smraw + SP_B);
    __half* sQ  = (__half*)(smraw + SQ_B);
    uint8_t* sM = (uint8_t*)(smraw + SM_B);
    uint32_t skv_b = smem_u32(sKV);

    int t = threadIdx.x;
    int wid = t >> 5, lane = t & 31;
    int grp = lane >> 2, q4 = lane & 3;
    const size_t rstr = 3*HID;
    const __half* base_b = qkv16 + (size_t)b*SS*rstr;

    {
        int row = t >> 3, seg = t & 7;
        uint4 qv4 = *(const uint4*)&base_b[(size_t)(q0 + row)*rstr + head*HD + seg*8];
        __half2 sc = __half2half2(__float2half(0.125f));
        __half2* q2 = (__half2*)&qv4;
        q2[0] = __hmul2(q2[0], sc); q2[1] = __hmul2(q2[1], sc);
        q2[2] = __hmul2(q2[2], sc); q2[3] = __hmul2(q2[3], sc);
        *(uint4*)&sQ[row*KVSH + seg*8] = qv4;
    }

    {
        const __half* ksrc = base_b + HID + head*HD;
#pragma unroll
        for (int i = 0; i < 10; i++){
            int idx = i*256 + t;
            int row = idx >> 3, seg = idx & 7;
            int jg = kbase + row;
            uint32_t nb = (jg >= 0 && jg < SS) ? 16u : 0u;
            int jc = jg < 0 ? 0 : (jg >= SS ? SS-1 : jg);
            CP_ASYNC16Z(skv_b + row*(KVSH*2) + seg*16, ksrc + (size_t)jc*rstr + seg*8, nb);
        }
        CP_COMMIT();
        if (t < KW){
            int jg = kbase + t;
            sM[t] = (jg >= 0 && jg < SS && km[b*SS + jg] != 0) ? 1 : 0;
        }
    }
    asm volatile("cp.async.wait_group 0;" ::: "memory");
    __syncthreads();

    {
        float acc[2][5][4];
#pragma unroll
        for (int mi = 0; mi < 2; mi++)
#pragma unroll
            for (int nt = 0; nt < 5; nt++)
#pragma unroll
                for (int r = 0; r < 4; r++) acc[mi][nt][r] = 0.f;

#pragma unroll
        for (int ks = 0; ks < 4; ks++){
            int k0 = ks*16;
            uint32_t af[2][4];
#pragma unroll
            for (int mi = 0; mi < 2; mi++){
                int bb = (mi*16 + grp)*KVSH + k0 + 2*q4;
                af[mi][0] = *(const uint32_t*)&sQ[bb];
                af[mi][1] = *(const uint32_t*)&sQ[bb + 8*KVSH];
                af[mi][2] = *(const uint32_t*)&sQ[bb + 8];
                af[mi][3] = *(const uint32_t*)&sQ[bb + 8*KVSH + 8];
            }
#pragma unroll
            for (int nt = 0; nt < 5; nt++){
                int n0 = wid*40 + nt*8;
                uint32_t bf[2];
                int bb = (n0 + grp)*KVSH + k0 + 2*q4;
                bf[0] = *(const uint32_t*)&sKV[bb];
                bf[1] = *(const uint32_t*)&sKV[bb + 8];
                mma_f16(acc[0][nt], af[0], bf);
                mma_f16(acc[1][nt], af[1], bf);
            }
        }
#pragma unroll
        for (int mi = 0; mi < 2; mi++){
            int r0 = mi*16 + grp;
#pragma unroll
            for (int nt = 0; nt < 5; nt++){
                int col = wid*40 + nt*8 + 2*q4;
                *(float2*)&sS[r0*SSTR + col]     = make_float2(acc[mi][nt][0], acc[mi][nt][1]);
                *(float2*)&sS[(r0+8)*SSTR + col] = make_float2(acc[mi][nt][2], acc[mi][nt][3]);
            }
        }
    }
    __syncthreads();

    {
        const __half* vsrc = base_b + 2*HID + head*HD;
#pragma unroll
        for (int i = 0; i < 10; i++){
            int idx = i*256 + t;
            int row = idx >> 3, seg = idx & 7;
            int jg = kbase + row;
            uint32_t nb = (jg >= 0 && jg < SS) ? 16u : 0u;
            int jc = jg < 0 ? 0 : (jg >= SS ? SS-1 : jg);
            CP_ASYNC16Z(skv_b + row*(KVSH*2) + seg*16, vsrc + (size_t)jc*rstr + seg*8, nb);
        }
        CP_COMMIT();
    }

    {
#pragma unroll
        for (int rr = 0; rr < 4; rr++){
            int qr = wid*4 + rr;
            float mx = -1e30f;
            for (int j = lane; j < KW; j += 32){
                bool ok = (j >= qr) && (j <= qr + 2*AW) && sM[j];
                float sc = ok ? sS[qr*SSTR + j] : -1e30f;
                sS[qr*SSTR + j] = sc;
                mx = fmaxf(mx, sc);
            }
#pragma unroll
            for (int o = 16; o > 0; o >>= 1) mx = fmaxf(mx, __shfl_xor_sync(~0u, mx, o));
            float sum = 0.f;
            for (int j = lane; j < KW; j += 32){
                float p = __expf(sS[qr*SSTR + j] - mx);
                sS[qr*SSTR + j] = p; sum += p;
            }
#pragma unroll
            for (int o = 16; o > 0; o >>= 1) sum += __shfl_xor_sync(~0u, sum, o);
            float inv = 1.f / sum;
            for (int j = lane; j < KW; j += 32)
                sP[qr*SPSTR + j] = __float2half(sS[qr*SSTR + j] * inv);
        }
    }
    asm volatile("cp.async.wait_group 0;" ::: "memory");
    __syncthreads();

    {
        int n0 = wid*8;
        float acc[2][4];
#pragma unroll
        for (int mi = 0; mi < 2; mi++)
#pragma unroll
            for (int r = 0; r < 4; r++) acc[mi][r] = 0.f;

#pragma unroll 5
        for (int ks = 0; ks < 20; ks++){
            int k0 = ks*16;
            uint32_t af[2][4], bf[2];
#pragma unroll
            for (int mi = 0; mi < 2; mi++){
                int bb = (mi*16 + grp)*SPSTR + k0 + 2*q4;
                af[mi][0] = *(const uint32_t*)&sP[bb];
                af[mi][1] = *(const uint32_t*)&sP[bb + 8*SPSTR];
                af[mi][2] = *(const uint32_t*)&sP[bb + 8];
                af[mi][3] = *(const uint32_t*)&sP[bb + 8*SPSTR + 8];
            }
            LDSM2T(bf, skv_b + (uint32_t)(k0 + (lane & 15))*(KVSH*2) + n0*2);
            mma_f16(acc[0], af[0], bf);
            mma_f16(acc[1], af[1], bf);
        }
#pragma unroll
        for (int mi = 0; mi < 2; mi++){
            int r0 = q0 + mi*16 + grp;
            int col = head*HD + n0 + 2*q4;
            *(__half2*)&ag16[((size_t)(b*SS + r0))*HID + col]     = __floats2half2_rn(acc[mi][0], acc[mi][1]);
            *(__half2*)&ag16[((size_t)(b*SS + r0 + 8))*HID + col] = __floats2half2_rn(acc[mi][2], acc[mi][3]);
        }
    }
}

// ---------------------------------------------------------------------------
// Host launcher
// ---------------------------------------------------------------------------
extern "C" void kernel_launch(void* const* d_in, const int* in_sizes, int n_in,
                              void* d_out, int out_size)
{
    (void)in_sizes; (void)n_in;
    const float* emb   = (const float*)d_in[0];
    const int*   amask = (const int*)  d_in[1];
    const float* pos   = (const float*)d_in[2];
    const float* tok   = (const float*)d_in[3];
    const float* eg    = (const float*)d_in[4];
    const float* eb    = (const float*)d_in[5];
    const float* Wq    = (const float*)d_in[6];
    const float* bq    = (const float*)d_in[7];
    const float* Wk    = (const float*)d_in[8];
    const float* bk    = (const float*)d_in[9];
    const float* Wv    = (const float*)d_in[10];
    const float* bv    = (const float*)d_in[11];
    const float* Wo    = (const float*)d_in[12];
    const float* bo    = (const float*)d_in[13];
    const float* ln1g  = (const float*)d_in[14];
    const float* ln1b  = (const float*)d_in[15];
    const float* Wi    = (const float*)d_in[16];
    const float* bi    = (const float*)d_in[17];
    const float* Wf    = (const float*)d_in[18];
    const float* bf    = (const float*)d_in[19];
    const float* ln2g  = (const float*)d_in[20];
    const float* ln2b  = (const float*)d_in[21];
    const float* Wp    = (const float*)d_in[22];
    const float* bp    = (const float*)d_in[23];

    float* scratch = nullptr;
    cudaGetSymbolAddress((void**)&scratch, g_scratch);
    float*  h     = scratch;
    __half* tmp16 = (__half*)(scratch + 1*(size_t)ACT);
    __half* qkv16 = (__half*)(scratch + 2*(size_t)ACT);
    __half* h16   = (__half*)(scratch + 4*(size_t)ACT);
    __half* a16   = (__half*)(scratch + 4*(size_t)ACT + ACT/2);
    __half* ffn16 = (__half*)(scratch + 5*(size_t)ACT);
    __half* WqkvT = (__half*)(scratch + 7*(size_t)ACT);
    __half* WoT   = WqkvT + 3*(size_t)WT_SM;
    __half* WiT   = WoT   + (size_t)WT_SM;
    __half* WfT   = WiT   + (size_t)WT_LG;

    cudaFuncSetAttribute(gemm_tc, cudaFuncAttributeMaxDynamicSharedMemorySize, GEMM_SMEM);
    cudaFuncSetAttribute(gemm_tc64, cudaFuncAttributeMaxDynamicSharedMemorySize, GEMM64_SMEM);
    cudaFuncSetAttribute(attn_kernel, cudaFuncAttributeMaxDynamicSharedMemorySize, ATT_SMEM);

    const size_t LSTR = (size_t)3*HID*HID;

    dim3 gqkv(3*HID/GBN, ROWS/GBM);
    dim3 g768n64(HID/64, ROWS/GBM);
    dim3 g3072(4*HID/GBN, ROWS/GBM);
    dim3 gattn(SS/QT, NH, BB);

    // Order so my launch #3 = first gemm_tc (harness offset +2 -> ncu -s 5).
    embed_ln_kernel<<<ROWS/8, 256>>>(emb, pos, tok, eg, eb, h, h16);                    // 0
    transpose_qkv<<<dim3(HID/32, HID/32, 3*NL), 256>>>(Wq, Wk, Wv, WqkvT);              // 1
    transpose_h<<<dim3(HID/32, HID/32, NL), 256>>>(Wo, WoT, HID, HID, (size_t)HID*HID); // 2
    gemm_tc<<<gqkv, 128, GEMM_SMEM>>>(h16, WqkvT, bq, bk, bv, qkv16, HID, 3*HID, 2|4);  // 3 <- profiled
    transpose_h<<<dim3(4*HID/32, HID/32, NL), 256>>>(Wi, WiT, HID, 4*HID, (size_t)4*HID*HID); // 4
    transpose_h<<<dim3(HID/32, 4*HID/32, NL), 256>>>(Wf, WfT, 4*HID, HID, (size_t)4*HID*HID); // 5

    for (int l = 0; l < NL; l++) {
        const size_t wofs  = (size_t)l * HID * HID;
        const size_t bofs  = (size_t)l * HID;
        const size_t wlofs = (size_t)l * HID * 4*HID;
        const size_t blofs = (size_t)l * 4*HID;

        if (l > 0)
            gemm_tc<<<gqkv, 128, GEMM_SMEM>>>(h16, WqkvT + l*LSTR, bq + bofs, bk + bofs, bv + bofs,
                                              qkv16, HID, 3*HID, 2|4);

        attn_kernel<<<gattn, 256, ATT_SMEM>>>(qkv16, amask, a16);

        gemm_tc64<<<g768n64, 128, GEMM64_SMEM>>>(a16, WoT + wofs, bo + bofs, tmp16, HID, HID, 2);
        add_ln_kernel<<<ROWS/8, 256>>>(h, tmp16, ln1g + bofs, ln1b + bofs, h, h16);

        gemm_tc<<<g3072, 128, GEMM_SMEM>>>(h16, WiT + wlofs, bi + blofs, bi, bi, ffn16, HID, 4*HID, 3);
        gemm_tc64<<<g768n64, 128, GEMM64_SMEM>>>(ffn16, WfT + wlofs, bf + bofs, tmp16, 4*HID, HID, 2);

        if (l < NL-1)
            add_ln_kernel<<<ROWS/8, 256>>>(h, tmp16, ln2g + bofs, ln2b + bofs, h, h16);
        else
            add_ln_final_kernel<<<ROWS/8, 256>>>(h, tmp16, ln2g + bofs, ln2b + bofs,
                                                 Wp, bp, (float*)d_out);
    }
    (void)out_size;
}

// round 16
// speedup vs baseline: 1.0039x; 1.0039x over previous
#include <cuda_runtime.h>
#include <cuda_fp16.h>
#include <math.h>
#include <stdint.h>

// Problem constants
#define BB   2
#define SS   4096
#define HID  768
#define NL   4
#define NH   12
#define HD   64
#define AW   128
#define ROWS (BB*SS)      // 8192

// ---------------------------------------------------------------------------
// Scratch
// ---------------------------------------------------------------------------
#define ACT (ROWS*HID)
#define WT_SM (NL*HID*HID)
#define WT_LG (NL*HID*4*HID)
__device__ float g_scratch[9*(size_t)ACT + 4*(size_t)WT_SM + 2*(size_t)WT_LG];

// ---------------------------------------------------------------------------
// helpers
// ---------------------------------------------------------------------------
__device__ __forceinline__ uint32_t smem_u32(const void* p){
    uint32_t a;
    asm("{ .reg .u64 t; cvta.to.shared.u64 t, %1; cvt.u32.u64 %0, t; }" : "=r"(a) : "l"(p));
    return a;
}
#define CP_ASYNC16(dst,src)      asm volatile("cp.async.cg.shared.global [%0], [%1], 16;" :: "r"(dst), "l"(src))
#define CP_ASYNC16Z(dst,src,nb)  asm volatile("cp.async.cg.shared.global [%0], [%1], 16, %2;" :: "r"(dst), "l"(src), "r"(nb))
#define CP_COMMIT() asm volatile("cp.async.commit_group;" ::: "memory")
#define LDSM4(r, a) \
    asm volatile("ldmatrix.sync.aligned.m8n8.x4.shared.b16 {%0,%1,%2,%3}, [%4];" \
        : "=r"((r)[0]),"=r"((r)[1]),"=r"((r)[2]),"=r"((r)[3]) : "r"(a))
#define LDSM2T(r, a) \
    asm volatile("ldmatrix.sync.aligned.m8n8.x2.trans.shared.b16 {%0,%1}, [%2];" \
        : "=r"((r)[0]),"=r"((r)[1]) : "r"(a))

__device__ __forceinline__ void mma_f16(float* d, const uint32_t* a, const uint32_t* b){
    asm volatile("mma.sync.aligned.m16n8k16.row.col.f32.f16.f16.f32 "
        "{%0,%1,%2,%3}, {%4,%5,%6,%7}, {%8,%9}, {%0,%1,%2,%3};"
        : "+f"(d[0]),"+f"(d[1]),"+f"(d[2]),"+f"(d[3])
        : "r"(a[0]),"r"(a[1]),"r"(a[2]),"r"(a[3]), "r"(b[0]),"r"(b[1]));
}
__device__ __forceinline__ float gelu_exact(float x){
    return 0.5f * x * (1.f + erff(x * 0.70710678118654752f));
}
__device__ __forceinline__ float wred_sum(float v){
#pragma unroll
    for (int o = 16; o > 0; o >>= 1) v += __shfl_xor_sync(~0u, v, o);
    return v;
}

// ---------------------------------------------------------------------------
// fp16 mma.sync GEMM 128x128, 256 threads = 8 warps (2x4), warp tile 64x32.
// 3-stage cp.async pipeline, 2 CTAs/SM (16 warps/SM for latency hiding).
// mode bits: 1 = gelu, 2 = fp16 output, 4 = qkv bias select
// ---------------------------------------------------------------------------
#define GBM 128
#define GBN 128
#define GBK 32
#define NSTG 3
#define STG  (2*GBM*80)              // 20480
#define GEMM_SMEM (NSTG*STG)         // 61440

__device__ __forceinline__ void load_chunk16(const __half* __restrict__ A, const __half* __restrict__ BT,
                                             int K, int bm, int bn, int c, uint32_t stage)
{
    int t = threadIdx.x;
    const __half* asrc = A  + (size_t)bm*K + (size_t)c*GBK;
    const __half* bsrc = BT + (size_t)bn*K + (size_t)c*GBK;
#pragma unroll
    for (int i = 0; i < 2; i++){
        int idx = i*256 + t;              // 0..511
        int row = idx >> 2, seg = idx & 3;
        CP_ASYNC16(stage + row*80 + seg*16, asrc + (size_t)row*K + seg*8);
    }
#pragma unroll
    for (int i = 0; i < 2; i++){
        int idx = i*256 + t;
        int row = idx >> 2, seg = idx & 3;
        CP_ASYNC16(stage + GBM*80 + row*80 + seg*16, bsrc + (size_t)row*K + seg*8);
    }
    CP_COMMIT();
}

__global__ __launch_bounds__(256, 2)
void gemm_tc(const __half* __restrict__ A, const __half* __restrict__ BT,
             const float* __restrict__ bias, const float* __restrict__ bK,
             const float* __restrict__ bV, void* __restrict__ Cv,
             int K, int N, int mode)
{
    extern __shared__ char smem[];
    int t = threadIdx.x;
    int wid = t >> 5, lane = t & 31;
    int grp = lane >> 2, q4 = lane & 3;
    int mw = (wid & 1) * 64, nw = (wid >> 1) * 32;
    int bm = blockIdx.y * GBM, bn = blockIdx.x * GBN;

    int lm = lane >> 3, lr = lane & 7;
    uint32_t aoff = (uint32_t)(((lm & 1)*8 + lr)*80 + (lm >> 1)*16);
    uint32_t boff = (uint32_t)(((lm >> 1)*8 + lr)*80 + (lm & 1)*16);

    float acc[4][4][4];
#pragma unroll
    for (int mi = 0; mi < 4; mi++)
#pragma unroll
        for (int ni = 0; ni < 4; ni++)
#pragma unroll
            for (int r = 0; r < 4; r++) acc[mi][ni][r] = 0.f;

    uint32_t sb = smem_u32(smem);
    const int NC = K / GBK;

    load_chunk16(A, BT, K, bm, bn, 0, sb);
    load_chunk16(A, BT, K, bm, bn, 1, sb + STG);

    for (int c = 0; c < NC; c++){
        int slot = c % NSTG;
        if (c + 1 < NC) { asm volatile("cp.async.wait_group 1;" ::: "memory"); }
        else            { asm volatile("cp.async.wait_group 0;" ::: "memory"); }
        __syncthreads();
        if (c + 2 < NC)
            load_chunk16(A, BT, K, bm, bn, c + 2, sb + ((c+2)%NSTG)*STG);

        uint32_t As_b = sb + slot*STG;
        uint32_t Bs_b = As_b + GBM*80;
#pragma unroll
        for (int ks = 0; ks < 2; ks++){
            uint32_t kb = ks*32;
            uint32_t af[4][4], bf[4][2];
#pragma unroll
            for (int mi = 0; mi < 4; mi++)
                LDSM4(af[mi], As_b + (mw + mi*16)*80 + aoff + kb);
#pragma unroll
            for (int p = 0; p < 2; p++){
                uint32_t r[4];
                LDSM4(r, Bs_b + (nw + p*16)*80 + boff + kb);
                bf[2*p][0] = r[0]; bf[2*p][1] = r[1];
                bf[2*p+1][0] = r[2]; bf[2*p+1][1] = r[3];
            }
#pragma unroll
            for (int mi = 0; mi < 4; mi++)
#pragma unroll
                for (int ni = 0; ni < 4; ni++)
                    mma_f16(acc[mi][ni], af[mi], bf[ni]);
        }
    }

    const float* bp = bias;
    int coff = 0;
    if (mode & 4){
        int sel = bn / HID;
        bp = (sel == 0) ? bias : (sel == 1 ? bK : bV);
        coff = sel * HID;
    }

    float* Cf = (float*)Cv;
    __half* Ch = (__half*)Cv;
#pragma unroll
    for (int mi = 0; mi < 4; mi++){
        int r0 = bm + mw + mi*16 + grp;
#pragma unroll
        for (int ni = 0; ni < 4; ni++){
            int col = bn + nw + ni*8 + 2*q4;
            float bx = bp[col - coff], by = bp[col + 1 - coff];
            float a0 = acc[mi][ni][0] + bx, a1 = acc[mi][ni][1] + by;
            float a2 = acc[mi][ni][2] + bx, a3 = acc[mi][ni][3] + by;
            if (mode & 1){
                a0 = gelu_exact(a0); a1 = gelu_exact(a1);
                a2 = gelu_exact(a2); a3 = gelu_exact(a3);
            }
            if (mode & 2){
                *(__half2*)&Ch[(size_t)r0*N + col]     = __floats2half2_rn(a0, a1);
                *(__half2*)&Ch[(size_t)(r0+8)*N + col] = __floats2half2_rn(a2, a3);
            } else {
                *(float2*)&Cf[(size_t)r0*N + col]     = make_float2(a0, a1);
                *(float2*)&Cf[(size_t)(r0+8)*N + col] = make_float2(a2, a3);
            }
        }
    }
}

// ---------------------------------------------------------------------------
// Weight transposes to fp16
// ---------------------------------------------------------------------------
__global__ __launch_bounds__(256)
void transpose_h(const float* __restrict__ in, __half* __restrict__ out,
                 int R, int C, size_t outStride)
{
    __shared__ float tile[32][33];
    const float* src = in  + (size_t)blockIdx.z * R * C;
    __half*      dst = out + (size_t)blockIdx.z * outStride;
    int r0 = blockIdx.y*32, c0 = blockIdx.x*32;
    int tx = threadIdx.x & 31, ty = threadIdx.x >> 5;
#pragma unroll
    for (int i = 0; i < 4; i++)
        tile[ty + i*8][tx] = src[(size_t)(r0 + ty + i*8)*C + c0 + tx];
    __syncthreads();
#pragma unroll
    for (int i = 0; i < 4; i++)
        dst[(size_t)(c0 + ty + i*8)*R + r0 + tx] = __float2half(tile[tx][ty + i*8]);
}

__global__ __launch_bounds__(256)
void transpose_qkv(const float* __restrict__ Wq, const float* __restrict__ Wk,
                   const float* __restrict__ Wv, __half* __restrict__ out)
{
    __shared__ float tile[32][33];
    int z = blockIdx.z;
    int m = z / NL, l = z % NL;
    const float* src = (m == 0 ? Wq : (m == 1 ? Wk : Wv)) + (size_t)l*HID*HID;
    __half* dst = out + (size_t)l*3*HID*HID + (size_t)m*HID*HID;
    int r0 = blockIdx.y*32, c0 = blockIdx.x*32;
    int tx = threadIdx.x & 31, ty = threadIdx.x >> 5;
#pragma unroll
    for (int i = 0; i < 4; i++)
        tile[ty + i*8][tx] = src[(size_t)(r0 + ty + i*8)*HID + c0 + tx];
    __syncthreads();
#pragma unroll
    for (int i = 0; i < 4; i++)
        dst[(size_t)(c0 + ty + i*8)*HID + r0 + tx] = __float2half(tile[tx][ty + i*8]);
}

// ---------------------------------------------------------------------------
// Warp-per-row LayerNorm kernels
// ---------------------------------------------------------------------------
__global__ __launch_bounds__(256)
void embed_ln_kernel(const float* __restrict__ emb, const float* __restrict__ pos,
                     const float* __restrict__ tok, const float* __restrict__ gam,
                     const float* __restrict__ bet, float* __restrict__ h,
                     __half* __restrict__ h16)
{
    int w = threadIdx.x >> 5, lane = threadIdx.x & 31;
    int r = blockIdx.x*8 + w;
    int s = r & (SS-1);
    const float* er = emb + (size_t)r*HID;
    const float* pr = pos + (size_t)(s+1)*HID;

    float x[24];
    float sum = 0.f;
#pragma unroll
    for (int i = 0; i < 6; i++){
        int c = i*128 + lane*4;
        float4 e = *(const float4*)&er[c];
        float4 p = *(const float4*)&pr[c];
        float4 tk = *(const float4*)&tok[c];
        x[i*4+0] = e.x + p.x + tk.x;
        x[i*4+1] = e.y + p.y + tk.y;
        x[i*4+2] = e.z + p.z + tk.z;
        x[i*4+3] = e.w + p.w + tk.w;
        sum += x[i*4+0] + x[i*4+1] + x[i*4+2] + x[i*4+3];
    }
    float mean = wred_sum(sum) * (1.f/HID);
    float vs = 0.f;
#pragma unroll
    for (int i = 0; i < 24; i++){ float d = x[i] - mean; vs += d*d; }
    float inv = rsqrtf(wred_sum(vs) * (1.f/HID) + 1e-12f);

    float* hr = h + (size_t)r*HID;
    __half* h16r = h16 + (size_t)r*HID;
#pragma unroll
    for (int i = 0; i < 6; i++){
        int c = i*128 + lane*4;
        float4 g = *(const float4*)&gam[c];
        float4 b = *(const float4*)&bet[c];
        float4 o;
        o.x = (x[i*4+0] - mean)*inv*g.x + b.x;
        o.y = (x[i*4+1] - mean)*inv*g.y + b.y;
        o.z = (x[i*4+2] - mean)*inv*g.z + b.z;
        o.w = (x[i*4+3] - mean)*inv*g.w + b.w;
        *(float4*)&hr[c] = o;
        *(__half2*)&h16r[c]   = __floats2half2_rn(o.x, o.y);
        *(__half2*)&h16r[c+2] = __floats2half2_rn(o.z, o.w);
    }
}

__global__ __launch_bounds__(256)
void add_ln_kernel(const float* __restrict__ hin, const __half* __restrict__ tin,
                   const float* __restrict__ gam, const float* __restrict__ bet,
                   float* __restrict__ hout, __half* __restrict__ h16)
{
    int w = threadIdx.x >> 5, lane = threadIdx.x & 31;
    int r = blockIdx.x*8 + w;
    const float* ar = hin + (size_t)r*HID;
    const __half* br = tin + (size_t)r*HID;

    float x[24];
    float sum = 0.f;
#pragma unroll
    for (int i = 0; i < 6; i++){
        int c = i*128 + lane*4;
        float4 a = *(const float4*)&ar[c];
        __half2 b0 = *(const __half2*)&br[c];
        __half2 b1 = *(const __half2*)&br[c+2];
        float2 f0 = __half22float2(b0), f1 = __half22float2(b1);
        x[i*4+0] = a.x + f0.x; x[i*4+1] = a.y + f0.y;
        x[i*4+2] = a.z + f1.x; x[i*4+3] = a.w + f1.y;
        sum += x[i*4+0] + x[i*4+1] + x[i*4+2] + x[i*4+3];
    }
    float mean = wred_sum(sum) * (1.f/HID);
    float vs = 0.f;
#pragma unroll
    for (int i = 0; i < 24; i++){ float d = x[i] - mean; vs += d*d; }
    float inv = rsqrtf(wred_sum(vs) * (1.f/HID) + 1e-12f);

    float* hr = hout + (size_t)r*HID;
    __half* h16r = h16 + (size_t)r*HID;
#pragma unroll
    for (int i = 0; i < 6; i++){
        int c = i*128 + lane*4;
        float4 g = *(const float4*)&gam[c];
        float4 b = *(const float4*)&bet[c];
        float4 o;
        o.x = (x[i*4+0] - mean)*inv*g.x + b.x;
        o.y = (x[i*4+1] - mean)*inv*g.y + b.y;
        o.z = (x[i*4+2] - mean)*inv*g.z + b.z;
        o.w = (x[i*4+3] - mean)*inv*g.w + b.w;
        *(float4*)&hr[c] = o;
        *(__half2*)&h16r[c]   = __floats2half2_rn(o.x, o.y);
        *(__half2*)&h16r[c+2] = __floats2half2_rn(o.z, o.w);
    }
}

// Last layer: residual + LN fused with classifier head.
__global__ __launch_bounds__(256)
void add_ln_final_kernel(const float* __restrict__ hin, const __half* __restrict__ tin,
                         const float* __restrict__ gam, const float* __restrict__ bet,
                         const float* __restrict__ Wp, const float* __restrict__ bp,
                         float* __restrict__ out)
{
    int w = threadIdx.x >> 5, lane = threadIdx.x & 31;
    int r = blockIdx.x*8 + w;
    const float* ar = hin + (size_t)r*HID;
    const __half* br = tin + (size_t)r*HID;

    float x[24];
    float sum = 0.f;
#pragma unroll
    for (int i = 0; i < 6; i++){
        int c = i*128 + lane*4;
        float4 a = *(const float4*)&ar[c];
        __half2 b0 = *(const __half2*)&br[c];
        __half2 b1 = *(const __half2*)&br[c+2];
        float2 f0 = __half22float2(b0), f1 = __half22float2(b1);
        x[i*4+0] = a.x + f0.x; x[i*4+1] = a.y + f0.y;
        x[i*4+2] = a.z + f1.x; x[i*4+3] = a.w + f1.y;
        sum += x[i*4+0] + x[i*4+1] + x[i*4+2] + x[i*4+3];
    }
    float mean = wred_sum(sum) * (1.f/HID);
    float vs = 0.f;
#pragma unroll
    for (int i = 0; i < 24; i++){ float d = x[i] - mean; vs += d*d; }
    float inv = rsqrtf(wred_sum(vs) * (1.f/HID) + 1e-12f);

    float dot = 0.f;
#pragma unroll
    for (int i = 0; i < 6; i++){
        int c = i*128 + lane*4;
        float4 g = *(const float4*)&gam[c];
        float4 b = *(const float4*)&bet[c];
        float4 wv = *(const float4*)&Wp[c];
        dot += ((x[i*4+0] - mean)*inv*g.x + b.x) * wv.x;
        dot += ((x[i*4+1] - mean)*inv*g.y + b.y) * wv.y;
        dot += ((x[i*4+2] - mean)*inv*g.z + b.z) * wv.z;
        dot += ((x[i*4+3] - mean)*inv*g.w + b.w) * wv.w;
    }
    dot = wred_sum(dot);
    if (lane == 0) out[r] = 1.f / (1.f + expf(-(dot + bp[0])));
}

// ---------------------------------------------------------------------------
// fp16 tensor-core sliding-window attention (2 CTAs/SM, aliased sQ/sP).
// ---------------------------------------------------------------------------
#define QT    32
#define KW    320
#define KVSH  72
#define SSTR  328
#define SPSTR 344
#define SKV_B  0
#define SS_B   (KW*KVSH*2)
#define SP_B   (SS_B + QT*SSTR*4)
#define SQ_B   SP_B
#define SM_B   (SP_B + QT*SPSTR*2)
#define ATT_SMEM (SM_B + KW)

__global__ __launch_bounds__(256)
void attn_kernel(const __half* __restrict__ qkv16, const int* __restrict__ km,
                 __half* __restrict__ ag16)
{
    int qt   = blockIdx.x;
    int head = blockIdx.y;
    int b    = blockIdx.z;
    int q0   = qt * QT;
    int kbase = q0 - AW;

    extern __shared__ char smraw[];
    __half* sKV = (__half*)(smraw + SKV_B);
    float*  sS  = (float*)(smraw + SS_B);
    __half* sP  = (__half*)(smraw + SP_B);
    __half* sQ  = (__half*)(smraw + SQ_B);
    uint8_t* sM = (uint8_t*)(smraw + SM_B);
    uint32_t skv_b = smem_u32(sKV);

    int t = threadIdx.x;
    int wid = t >> 5, lane = t & 31;
    int grp = lane >> 2, q4 = lane & 3;
    const size_t rstr = 3*HID;
    const __half* base_b = qkv16 + (size_t)b*SS*rstr;

    {
        int row = t >> 3, seg = t & 7;
        uint4 qv4 = *(const uint4*)&base_b[(size_t)(q0 + row)*rstr + head*HD + seg*8];
        __half2 sc = __half2half2(__float2half(0.125f));
        __half2* q2 = (__half2*)&qv4;
        q2[0] = __hmul2(q2[0], sc); q2[1] = __hmul2(q2[1], sc);
        q2[2] = __hmul2(q2[2], sc); q2[3] = __hmul2(q2[3], sc);
        *(uint4*)&sQ[row*KVSH + seg*8] = qv4;
    }

    {
        const __half* ksrc = base_b + HID + head*HD;
#pragma unroll
        for (int i = 0; i < 10; i++){
            int idx = i*256 + t;
            int row = idx >> 3, seg = idx & 7;
            int jg = kbase + row;
            uint32_t nb = (jg >= 0 && jg < SS) ? 16u : 0u;
            int jc = jg < 0 ? 0 : (jg >= SS ? SS-1 : jg);
            CP_ASYNC16Z(skv_b + row*(KVSH*2) + seg*16, ksrc + (size_t)jc*rstr + seg*8, nb);
        }
        CP_COMMIT();
        if (t < KW){
            int jg = kbase + t;
            sM[t] = (jg >= 0 && jg < SS && km[b*SS + jg] != 0) ? 1 : 0;
        }
    }
    asm volatile("cp.async.wait_group 0;" ::: "memory");
    __syncthreads();

    {
        float acc[2][5][4];
#pragma unroll
        for (int mi = 0; mi < 2; mi++)
#pragma unroll
            for (int nt = 0; nt < 5; nt++)
#pragma unroll
                for (int r = 0; r < 4; r++) acc[mi][nt][r] = 0.f;

#pragma unroll
        for (int ks = 0; ks < 4; ks++){
            int k0 = ks*16;
            uint32_t af[2][4];
#pragma unroll
            for (int mi = 0; mi < 2; mi++){
                int bb = (mi*16 + grp)*KVSH + k0 + 2*q4;
                af[mi][0] = *(const uint32_t*)&sQ[bb];
                af[mi][1] = *(const uint32_t*)&sQ[bb + 8*KVSH];
                af[mi][2] = *(const uint32_t*)&sQ[bb + 8];
                af[mi][3] = *(const uint32_t*)&sQ[bb + 8*KVSH + 8];
            }
#pragma unroll
            for (int nt = 0; nt < 5; nt++){
                int n0 = wid*40 + nt*8;
                uint32_t bf[2];
                int bb = (n0 + grp)*KVSH + k0 + 2*q4;
                bf[0] = *(const uint32_t*)&sKV[bb];
                bf[1] = *(const uint32_t*)&sKV[bb + 8];
                mma_f16(acc[0][nt], af[0], bf);
                mma_f16(acc[1][nt], af[1], bf);
            }
        }
#pragma unroll
        for (int mi = 0; mi < 2; mi++){
            int r0 = mi*16 + grp;
#pragma unroll
            for (int nt = 0; nt < 5; nt++){
                int col = wid*40 + nt*8 + 2*q4;
                *(float2*)&sS[r0*SSTR + col]     = make_float2(acc[mi][nt][0], acc[mi][nt][1]);
                *(float2*)&sS[(r0+8)*SSTR + col] = make_float2(acc[mi][nt][2], acc[mi][nt][3]);
            }
        }
    }
    __syncthreads();

    {
        const __half* vsrc = base_b + 2*HID + head*HD;
#pragma unroll
        for (int i = 0; i < 10; i++){
            int idx = i*256 + t;
            int row = idx >> 3, seg = idx & 7;
            int jg = kbase + row;
            uint32_t nb = (jg >= 0 && jg < SS) ? 16u : 0u;
            int jc = jg < 0 ? 0 : (jg >= SS ? SS-1 : jg);
            CP_ASYNC16Z(skv_b + row*(KVSH*2) + seg*16, vsrc + (size_t)jc*rstr + seg*8, nb);
        }
        CP_COMMIT();
    }

    {
#pragma unroll
        for (int rr = 0; rr < 4; rr++){
            int qr = wid*4 + rr;
            float mx = -1e30f;
            for (int j = lane; j < KW; j += 32){
                bool ok = (j >= qr) && (j <= qr + 2*AW) && sM[j];
                float sc = ok ? sS[qr*SSTR + j] : -1e30f;
                sS[qr*SSTR + j] = sc;
                mx = fmaxf(mx, sc);
            }
#pragma unroll
            for (int o = 16; o > 0; o >>= 1) mx = fmaxf(mx, __shfl_xor_sync(~0u, mx, o));
            float sum = 0.f;
            for (int j = lane; j < KW; j += 32){
                float p = __expf(sS[qr*SSTR + j] - mx);
                sS[qr*SSTR + j] = p; sum += p;
            }
#pragma unroll
            for (int o = 16; o > 0; o >>= 1) sum += __shfl_xor_sync(~0u, sum, o);
            float inv = 1.f / sum;
            for (int j = lane; j < KW; j += 32)
                sP[qr*SPSTR + j] = __float2half(sS[qr*SSTR + j] * inv);
        }
    }
    asm volatile("cp.async.wait_group 0;" ::: "memory");
    __syncthreads();

    {
        int n0 = wid*8;
        float acc[2][4];
#pragma unroll
        for (int mi = 0; mi < 2; mi++)
#pragma unroll
            for (int r = 0; r < 4; r++) acc[mi][r] = 0.f;

#pragma unroll 5
        for (int ks = 0; ks < 20; ks++){
            int k0 = ks*16;
            uint32_t af[2][4], bf[2];
#pragma unroll
            for (int mi = 0; mi < 2; mi++){
                int bb = (mi*16 + grp)*SPSTR + k0 + 2*q4;
                af[mi][0] = *(const uint32_t*)&sP[bb];
                af[mi][1] = *(const uint32_t*)&sP[bb + 8*SPSTR];
                af[mi][2] = *(const uint32_t*)&sP[bb + 8];
                af[mi][3] = *(const uint32_t*)&sP[bb + 8*SPSTR + 8];
            }
            LDSM2T(bf, skv_b + (uint32_t)(k0 + (lane & 15))*(KVSH*2) + n0*2);
            mma_f16(acc[0], af[0], bf);
            mma_f16(acc[1], af[1], bf);
        }
#pragma unroll
        for (int mi = 0; mi < 2; mi++){
            int r0 = q0 + mi*16 + grp;
            int col = head*HD + n0 + 2*q4;
            *(__half2*)&ag16[((size_t)(b*SS + r0))*HID + col]     = __floats2half2_rn(acc[mi][0], acc[mi][1]);
            *(__half2*)&ag16[((size_t)(b*SS + r0 + 8))*HID + col] = __floats2half2_rn(acc[mi][2], acc[mi][3]);
        }
    }
}

// ---------------------------------------------------------------------------
// Host launcher
// ---------------------------------------------------------------------------
extern "C" void kernel_launch(void* const* d_in, const int* in_sizes, int n_in,
                              void* d_out, int out_size)
{
    (void)in_sizes; (void)n_in;
    const float* emb   = (const float*)d_in[0];
    const int*   amask = (const int*)  d_in[1];
    const float* pos   = (const float*)d_in[2];
    const float* tok   = (const float*)d_in[3];
    const float* eg    = (const float*)d_in[4];
    const float* eb    = (const float*)d_in[5];
    const float* Wq    = (const float*)d_in[6];
    const float* bq    = (const float*)d_in[7];
    const float* Wk    = (const float*)d_in[8];
    const float* bk    = (const float*)d_in[9];
    const float* Wv    = (const float*)d_in[10];
    const float* bv    = (const float*)d_in[11];
    const float* Wo    = (const float*)d_in[12];
    const float* bo    = (const float*)d_in[13];
    const float* ln1g  = (const float*)d_in[14];
    const float* ln1b  = (const float*)d_in[15];
    const float* Wi    = (const float*)d_in[16];
    const float* bi    = (const float*)d_in[17];
    const float* Wf    = (const float*)d_in[18];
    const float* bf    = (const float*)d_in[19];
    const float* ln2g  = (const float*)d_in[20];
    const float* ln2b  = (const float*)d_in[21];
    const float* Wp    = (const float*)d_in[22];
    const float* bp    = (const float*)d_in[23];

    float* scratch = nullptr;
    cudaGetSymbolAddress((void**)&scratch, g_scratch);
    float*  h     = scratch;
    __half* tmp16 = (__half*)(scratch + 1*(size_t)ACT);
    __half* qkv16 = (__half*)(scratch + 2*(size_t)ACT);
    __half* h16   = (__half*)(scratch + 4*(size_t)ACT);
    __half* a16   = (__half*)(scratch + 4*(size_t)ACT + ACT/2);
    __half* ffn16 = (__half*)(scratch + 5*(size_t)ACT);
    __half* WqkvT = (__half*)(scratch + 7*(size_t)ACT);
    __half* WoT   = WqkvT + 3*(size_t)WT_SM;
    __half* WiT   = WoT   + (size_t)WT_SM;
    __half* WfT   = WiT   + (size_t)WT_LG;

    cudaFuncSetAttribute(gemm_tc, cudaFuncAttributeMaxDynamicSharedMemorySize, GEMM_SMEM);
    cudaFuncSetAttribute(attn_kernel, cudaFuncAttributeMaxDynamicSharedMemorySize, ATT_SMEM);

    const size_t LSTR = (size_t)3*HID*HID;

    dim3 gqkv(3*HID/GBN, ROWS/GBM);    // (18, 64)
    dim3 g768(HID/GBN, ROWS/GBM);      // (6, 64)
    dim3 g3072(4*HID/GBN, ROWS/GBM);   // (24, 64)
    dim3 gattn(SS/QT, NH, BB);

    // keep my launch #3 = first gemm_tc (profiled slot)
    embed_ln_kernel<<<ROWS/8, 256>>>(emb, pos, tok, eg, eb, h, h16);                    // 0
    transpose_qkv<<<dim3(HID/32, HID/32, 3*NL), 256>>>(Wq, Wk, Wv, WqkvT);              // 1
    transpose_h<<<dim3(HID/32, HID/32, NL), 256>>>(Wo, WoT, HID, HID, (size_t)HID*HID); // 2
    gemm_tc<<<gqkv, 256, GEMM_SMEM>>>(h16, WqkvT, bq, bk, bv, qkv16, HID, 3*HID, 2|4);  // 3 <- profiled
    transpose_h<<<dim3(4*HID/32, HID/32, NL), 256>>>(Wi, WiT, HID, 4*HID, (size_t)4*HID*HID); // 4
    transpose_h<<<dim3(HID/32, 4*HID/32, NL), 256>>>(Wf, WfT, 4*HID, HID, (size_t)4*HID*HID); // 5

    for (int l = 0; l < NL; l++) {
        const size_t wofs  = (size_t)l * HID * HID;
        const size_t bofs  = (size_t)l * HID;
        const size_t wlofs = (size_t)l * HID * 4*HID;
        const size_t blofs = (size_t)l * 4*HID;

        if (l > 0)
            gemm_tc<<<gqkv, 256, GEMM_SMEM>>>(h16, WqkvT + l*LSTR, bq + bofs, bk + bofs, bv + bofs,
                                              qkv16, HID, 3*HID, 2|4);

        attn_kernel<<<gattn, 256, ATT_SMEM>>>(qkv16, amask, a16);

        gemm_tc<<<g768, 256, GEMM_SMEM>>>(a16, WoT + wofs, bo + bofs, bo, bo, tmp16, HID, HID, 2);
        add_ln_kernel<<<ROWS/8, 256>>>(h, tmp16, ln1g + bofs, ln1b + bofs, h, h16);

        gemm_tc<<<g3072, 256, GEMM_SMEM>>>(h16, WiT + wlofs, bi + blofs, bi, bi, ffn16, HID, 4*HID, 3);
        gemm_tc<<<g768, 256, GEMM_SMEM>>>(ffn16, WfT + wlofs, bf + bofs, bf, bf, tmp16, 4*HID, HID, 2);

        if (l < NL-1)
            add_ln_kernel<<<ROWS/8, 256>>>(h, tmp16, ln2g + bofs, ln2b + bofs, h, h16);
        else
            add_ln_final_kernel<<<ROWS/8, 256>>>(h, tmp16, ln2g + bofs, ln2b + bofs,
                                                 Wp, bp, (float*)d_out);
    }
    (void)out_size;
}